// round 11
// baseline (speedup 1.0000x reference)
#include <cuda_runtime.h>
#include <cuda_fp16.h>
#include <cstdint>

#define NN 50000
#define DD 64
#define NE 800000

// ---- scratch (__device__ globals; allocation-free rule) ----
__device__ int   g_csrc[NE];     // CSR: source node per edge, grouped by dst
__device__ int   g_rank[NE];     // rank of edge within its dst bucket
__device__ int   g_deg[NN];      // invariant: zero at entry of every call
__device__ int   g_off[NN + 1];
__device__ __align__(16) __half g_t[NN * DD];  // t = act(X) @ W_nbr  (fp16)
__device__ __align__(16) float  g_h[NN * DD];  // hidden activations  (fp32)

// ---------------------------------------------------------------------------
// Per-block int64-vs-int32 detection (odd 32-bit words all zero => int64).
// ---------------------------------------------------------------------------
__device__ __forceinline__ int detect_idx64(const unsigned* words) {
    __shared__ int nz;
    if (threadIdx.x == 0) nz = 0;
    __syncthreads();
    if (threadIdx.x < 256 && words[2 * threadIdx.x + 1] != 0u) nz = 1;
    __syncthreads();
    return nz ? 0 : 1;
}

// ---------------------------------------------------------------------------
// hist + rank: the ONLY atomic pass. rank = old degree count.
// ---------------------------------------------------------------------------
__global__ void __launch_bounds__(256) hist_rank_kernel(const void* __restrict__ idx, int E) {
    int idx64 = detect_idx64((const unsigned*)idx);
    int i = blockIdx.x * blockDim.x + threadIdx.x;
    if (i >= E) return;
    int d;
    if (idx64) d = (int)((const long long*)idx)[(size_t)E + i];
    else       d = ((const int*)idx)[(size_t)E + i];
    g_rank[i] = atomicAdd(&g_deg[d], 1);
}

// ---------------------------------------------------------------------------
// Single-block exclusive scan of g_deg -> g_off (1024 threads, ~49 elems each).
// Also re-zeroes g_deg (restores the call invariant) and sets g_off[n] = E.
// ---------------------------------------------------------------------------
__global__ void __launch_bounds__(1024) scan_kernel(int n, int E) {
    int tid = threadIdx.x;
    int chunk = (n + 1023) >> 10;
    int start = tid * chunk;
    int end = start + chunk; if (end > n) end = n;

    int sum = 0;
    for (int i = start; i < end; i++) sum += g_deg[i];

    // block-wide exclusive scan of per-thread sums
    __shared__ int warp_sums[32];
    int lane = tid & 31, wid = tid >> 5;
    int v = sum;
#pragma unroll
    for (int o = 1; o < 32; o <<= 1) {
        int u = __shfl_up_sync(0xFFFFFFFFu, v, o);
        if (lane >= o) v += u;
    }
    if (lane == 31) warp_sums[wid] = v;
    __syncthreads();
    if (wid == 0) {
        int w = warp_sums[lane];
#pragma unroll
        for (int o = 1; o < 32; o <<= 1) {
            int u = __shfl_up_sync(0xFFFFFFFFu, w, o);
            if (lane >= o) w += u;
        }
        warp_sums[lane] = w;
    }
    __syncthreads();
    int excl = v - sum + (wid > 0 ? warp_sums[wid - 1] : 0);

    int run = excl;
    for (int i = start; i < end; i++) {
        int d = g_deg[i];
        g_off[i] = run;
        run += d;
        g_deg[i] = 0;           // restore invariant for next call
    }
    if (tid == 0) g_off[n] = E;
}

// ---------------------------------------------------------------------------
// place: no atomics. pos = off[dst] + rank.
// ---------------------------------------------------------------------------
__global__ void __launch_bounds__(256) place_kernel(const void* __restrict__ idx, int E) {
    int idx64 = detect_idx64((const unsigned*)idx);
    int e = blockIdx.x * blockDim.x + threadIdx.x;
    if (e >= E) return;
    int s, d;
    if (idx64) {
        const long long* p = (const long long*)idx;
        s = (int)p[e];
        d = (int)p[(size_t)E + e];
    } else {
        const int* p = (const int*)idx;
        s = p[e];
        d = p[(size_t)E + e];
    }
    g_csrc[__ldg(&g_off[d]) + g_rank[e]] = s;
}

// ---------------------------------------------------------------------------
// Dual GEMM via mma.sync.m16n8k16 (fp16 in, fp32 acc).
// Block: 128 M-rows, 256 threads (8 warps = 4m x 2n; warp tile 32x64).
// B = [Wroot | Wnbr] staged as 64x128 fp16. warp_n==0 -> Omain (fp32 + bias),
// warp_n==1 -> Ot (fp16). SMEM XOR-swizzled for conflict-free ldmatrix.
// ---------------------------------------------------------------------------
__device__ __forceinline__ uint32_t smem_u32(const void* p) {
    return (uint32_t)__cvta_generic_to_shared(p);
}

__device__ __forceinline__ void ldm_x4(uint32_t* r, uint32_t addr) {
    asm volatile("ldmatrix.sync.aligned.m8n8.x4.shared.b16 {%0,%1,%2,%3}, [%4];"
                 : "=r"(r[0]), "=r"(r[1]), "=r"(r[2]), "=r"(r[3]) : "r"(addr));
}
__device__ __forceinline__ void ldm_x4_t(uint32_t* r, uint32_t addr) {
    asm volatile("ldmatrix.sync.aligned.m8n8.x4.trans.shared.b16 {%0,%1,%2,%3}, [%4];"
                 : "=r"(r[0]), "=r"(r[1]), "=r"(r[2]), "=r"(r[3]) : "r"(addr));
}
__device__ __forceinline__ void mma16816(float* c, const uint32_t* a,
                                         uint32_t b0, uint32_t b1) {
    asm volatile(
        "mma.sync.aligned.m16n8k16.row.col.f32.f16.f16.f32 "
        "{%0,%1,%2,%3}, {%4,%5,%6,%7}, {%8,%9}, {%0,%1,%2,%3};"
        : "+f"(c[0]), "+f"(c[1]), "+f"(c[2]), "+f"(c[3])
        : "r"(a[0]), "r"(a[1]), "r"(a[2]), "r"(a[3]), "r"(b0), "r"(b1));
}

template <bool RELU>
__global__ void __launch_bounds__(256) gemm_dual_kernel(
    const float* __restrict__ X,
    const float* __restrict__ Wroot,
    const float* __restrict__ Wnbr,
    const float* __restrict__ bias,
    float* __restrict__ Omain,
    __half* __restrict__ Ot,
    int n)
{
    __shared__ __align__(16) __half sX[128 * 64];    // row stride 64h = 8 chunks
    __shared__ __align__(16) __half sW[64 * 128];    // row stride 128h = 16 chunks
    __shared__ float sBias[64];

    const int tid = threadIdx.x;
    const int row0 = blockIdx.x * 128;

    // ---- stage X (fp32 -> fp16, optional relu, swizzled): 1024 chunks ----
#pragma unroll
    for (int i = 0; i < 4; i++) {
        int idx = tid + 256 * i;          // 0..1023
        int r = idx >> 3;                 // local row 0..127
        int c8 = idx & 7;                 // 16B chunk 0..7
        int grow = row0 + r;
        float4 v0 = make_float4(0.f, 0.f, 0.f, 0.f), v1 = v0;
        if (grow < n) {
            const float4* xr = (const float4*)X + (size_t)grow * 16;
            v0 = xr[c8 * 2]; v1 = xr[c8 * 2 + 1];
        }
        if (RELU) {
            v0.x = fmaxf(v0.x, 0.f); v0.y = fmaxf(v0.y, 0.f);
            v0.z = fmaxf(v0.z, 0.f); v0.w = fmaxf(v0.w, 0.f);
            v1.x = fmaxf(v1.x, 0.f); v1.y = fmaxf(v1.y, 0.f);
            v1.z = fmaxf(v1.z, 0.f); v1.w = fmaxf(v1.w, 0.f);
        }
        __half2 hp[4];
        hp[0] = __floats2half2_rn(v0.x, v0.y);
        hp[1] = __floats2half2_rn(v0.z, v0.w);
        hp[2] = __floats2half2_rn(v1.x, v1.y);
        hp[3] = __floats2half2_rn(v1.z, v1.w);
        *(uint4*)&sX[r * 64 + ((c8 ^ (r & 7)) << 3)] = *(uint4*)hp;
    }

    // ---- stage W = [Wroot | Wnbr] (64 rows x 16 chunks, swizzled) ----
#pragma unroll
    for (int i = 0; i < 4; i++) {
        int idx = tid + 256 * i;          // 0..1023
        int k = idx >> 4;                 // 0..63
        int c16 = idx & 15;               // chunk 0..15
        const float* src = (c16 < 8) ? (Wroot + k * 64 + c16 * 8)
                                     : (Wnbr + k * 64 + (c16 - 8) * 8);
        float4 v0 = ((const float4*)src)[0];
        float4 v1 = ((const float4*)src)[1];
        __half2 hp[4];
        hp[0] = __floats2half2_rn(v0.x, v0.y);
        hp[1] = __floats2half2_rn(v0.z, v0.w);
        hp[2] = __floats2half2_rn(v1.x, v1.y);
        hp[3] = __floats2half2_rn(v1.z, v1.w);
        *(uint4*)&sW[k * 128 + ((c16 ^ (k & 7)) << 3)] = *(uint4*)hp;
    }
    if (tid < 64) sBias[tid] = bias[tid];
    __syncthreads();

    // ---- mma phase ----
    const int lane = tid & 31;
    const int wid = tid >> 5;
    const int warp_m = wid & 3;          // 0..3 -> m 32-row slab
    const int warp_n = wid >> 2;         // 0: Omain cols 0-63, 1: Ot
    const int m_base = warp_m * 32;
    const int n_base = warp_n * 64;

    float c[2][8][4];
#pragma unroll
    for (int tm = 0; tm < 2; tm++)
#pragma unroll
        for (int nt = 0; nt < 8; nt++)
#pragma unroll
            for (int q = 0; q < 4; q++) c[tm][nt][q] = 0.f;

    const uint32_t sX_base = smem_u32(sX);
    const uint32_t sW_base = smem_u32(sW);

#pragma unroll
    for (int ks = 0; ks < 4; ks++) {
        uint32_t a[2][4];
#pragma unroll
        for (int tm = 0; tm < 2; tm++) {
            int rl = m_base + tm * 16 + (lane & 15);
            int kchunk = ks * 2 + (lane >> 4);
            uint32_t off = rl * 64 + ((kchunk ^ (rl & 7)) << 3);
            ldm_x4(a[tm], sX_base + off * 2);
        }
        uint32_t b[4][4];
#pragma unroll
        for (int np = 0; np < 4; np++) {
            int rk = ks * 16 + (lane & 15);
            int nchunk = (n_base >> 3) + np * 2 + (lane >> 4);
            uint32_t off = rk * 128 + ((nchunk ^ (rk & 7)) << 3);
            ldm_x4_t(b[np], sW_base + off * 2);
        }
#pragma unroll
        for (int tm = 0; tm < 2; tm++)
#pragma unroll
            for (int np = 0; np < 4; np++) {
                mma16816(c[tm][2 * np],     a[tm], b[np][0], b[np][1]);
                mma16816(c[tm][2 * np + 1], a[tm], b[np][2], b[np][3]);
            }
    }

    // ---- epilogue ----
    const int groupID = lane >> 2;
    const int tq = lane & 3;
#pragma unroll
    for (int tm = 0; tm < 2; tm++) {
#pragma unroll
        for (int nt = 0; nt < 8; nt++) {
            int col = nt * 8 + tq * 2;               // within this warp's 64 cols
            int r0g = row0 + m_base + tm * 16 + groupID;
            int r1g = r0g + 8;
            if (warp_n == 0) {
                float2 bv = *(float2*)&sBias[col];
                if (r0g < n) {
                    float2 o = make_float2(c[tm][nt][0] + bv.x, c[tm][nt][1] + bv.y);
                    *(float2*)(Omain + (size_t)r0g * 64 + col) = o;
                }
                if (r1g < n) {
                    float2 o = make_float2(c[tm][nt][2] + bv.x, c[tm][nt][3] + bv.y);
                    *(float2*)(Omain + (size_t)r1g * 64 + col) = o;
                }
            } else {
                if (r0g < n)
                    *(__half2*)(Ot + (size_t)r0g * 64 + col) =
                        __floats2half2_rn(c[tm][nt][0], c[tm][nt][1]);
                if (r1g < n)
                    *(__half2*)(Ot + (size_t)r1g * 64 + col) =
                        __floats2half2_rn(c[tm][nt][2], c[tm][nt][3]);
            }
        }
    }
}

// ---------------------------------------------------------------------------
// CSR gather-aggregate (fp16 t): 8 lanes per node, 16B (8 halves) per lane.
// out[i] += sum_{e: dst==i} t[csrc[e]]  — fp32 accumulate.
// ---------------------------------------------------------------------------
__global__ void __launch_bounds__(256) agg_kernel(
    const __half* __restrict__ t, float* __restrict__ out, int n)
{
    int gid = blockIdx.x * blockDim.x + threadIdx.x;
    int node = gid >> 3;
    if (node >= n) return;
    int part = threadIdx.x & 7;

    int start = g_off[node];
    int end   = g_off[node + 1];

    const uint4* tH = (const uint4*)t;
    float acc[8] = {0.f, 0.f, 0.f, 0.f, 0.f, 0.f, 0.f, 0.f};

    int j = start;
    for (; j + 4 <= end; j += 4) {
        int s0 = __ldg(&g_csrc[j]);
        int s1 = __ldg(&g_csrc[j + 1]);
        int s2 = __ldg(&g_csrc[j + 2]);
        int s3 = __ldg(&g_csrc[j + 3]);
        uint4 r0 = tH[(size_t)s0 * 8 + part];
        uint4 r1 = tH[(size_t)s1 * 8 + part];
        uint4 r2 = tH[(size_t)s2 * 8 + part];
        uint4 r3 = tH[(size_t)s3 * 8 + part];
        const uint4 rr[4] = {r0, r1, r2, r3};
#pragma unroll
        for (int q = 0; q < 4; q++) {
            const __half2* hp = (const __half2*)&rr[q];
#pragma unroll
            for (int cidx = 0; cidx < 4; cidx++) {
                float2 f = __half22float2(hp[cidx]);
                acc[2 * cidx]     += f.x;
                acc[2 * cidx + 1] += f.y;
            }
        }
    }
    for (; j < end; j++) {
        int s = __ldg(&g_csrc[j]);
        uint4 r = tH[(size_t)s * 8 + part];
        const __half2* hp = (const __half2*)&r;
#pragma unroll
        for (int cidx = 0; cidx < 4; cidx++) {
            float2 f = __half22float2(hp[cidx]);
            acc[2 * cidx]     += f.x;
            acc[2 * cidx + 1] += f.y;
        }
    }

    float4* o4 = (float4*)(out + (size_t)node * 64 + part * 8);
    float4 c0 = o4[0], c1 = o4[1];
    c0.x += acc[0]; c0.y += acc[1]; c0.z += acc[2]; c0.w += acc[3];
    c1.x += acc[4]; c1.y += acc[5]; c1.z += acc[6]; c1.w += acc[7];
    o4[0] = c0; o4[1] = c1;
}

// ---------------------------------------------------------------------------
extern "C" void kernel_launch(void* const* d_in, const int* in_sizes, int n_in,
                              void* d_out, int out_size)
{
    const float* x      = (const float*)d_in[0];
    const void*  eidx   = d_in[1];
    const float* W1root = (const float*)d_in[2];
    const float* W1nbr  = (const float*)d_in[3];
    const float* b1     = (const float*)d_in[4];
    const float* W2root = (const float*)d_in[5];
    const float* W2nbr  = (const float*)d_in[6];
    const float* b2     = (const float*)d_in[7];
    float* out = (float*)d_out;

    const int n = in_sizes[0] / DD;     // 50000
    const int E = in_sizes[1] / 2;      // 800000

    float* hptr;
    __half* tptr;
    cudaGetSymbolAddress((void**)&hptr, g_h);
    cudaGetSymbolAddress((void**)&tptr, g_t);

    const int edge_blocks = (E + 255) / 256;
    const int gemm_blocks = (n + 127) / 128;
    const int agg_blocks  = (n * 8 + 255) / 256;

    static cudaStream_t s_side = nullptr;
    static cudaEvent_t  ev_fork = nullptr, ev_join = nullptr;
    if (s_side == nullptr) {
        cudaStreamCreateWithFlags(&s_side, cudaStreamNonBlocking);
        cudaEventCreateWithFlags(&ev_fork, cudaEventDisableTiming);
        cudaEventCreateWithFlags(&ev_join, cudaEventDisableTiming);
    }

    // ---- fork: CSR build on side stream, concurrent with gemm1 ----
    cudaEventRecord(ev_fork, cudaStreamPerThread);
    cudaStreamWaitEvent(s_side, ev_fork, 0);

    hist_rank_kernel<<<edge_blocks, 256, 0, s_side>>>(eidx, E);
    scan_kernel     <<<1, 1024, 0, s_side>>>(n, E);
    place_kernel    <<<edge_blocks, 256, 0, s_side>>>(eidx, E);
    cudaEventRecord(ev_join, s_side);

    // ---- main stream: layer-1 GEMM in parallel with CSR build ----
    gemm_dual_kernel<false><<<gemm_blocks, 256>>>(x, W1root, W1nbr, b1, hptr, tptr, n);

    // join: agg1 needs both CSR and t1
    cudaStreamWaitEvent(cudaStreamPerThread, ev_join, 0);
    agg_kernel<<<agg_blocks, 256>>>(tptr, hptr, n);

    // ---- Layer 2 ----
    gemm_dual_kernel<true><<<gemm_blocks, 256>>>(hptr, W2root, W2nbr, b2, out, tptr, n);
    agg_kernel<<<agg_blocks, 256>>>(tptr, out, n);
}

// round 12
// speedup vs baseline: 2.0960x; 2.0960x over previous
#include <cuda_runtime.h>
#include <cuda_fp16.h>
#include <cstdint>

#define NN 50000
#define DD 64
#define NE 800000

// ---- scratch (__device__ globals; allocation-free rule) ----
__device__ int   g_csrc[NE];     // CSR: source node per edge, grouped by dst
__device__ int   g_rank[NE];     // rank of edge within its dst bucket
__device__ int   g_deg[NN];      // invariant: zero at entry of every call
__device__ int   g_off[NN];      // per-block-exclusive offsets
__device__ int   g_bsum[256];    // global-exclusive block offsets
__device__ int   g_done;         // invariant: zero at entry of every call
__device__ __align__(16) __half g_t[NN * DD];  // t = act(X) @ W_nbr  (fp16)
__device__ __align__(16) float  g_h[NN * DD];  // hidden activations  (fp32)

// ---------------------------------------------------------------------------
// Per-block int64-vs-int32 detection (odd 32-bit words all zero => int64).
// ---------------------------------------------------------------------------
__device__ __forceinline__ int detect_idx64(const unsigned* words) {
    __shared__ int nz;
    if (threadIdx.x == 0) nz = 0;
    __syncthreads();
    if (threadIdx.x < 256 && words[2 * threadIdx.x + 1] != 0u) nz = 1;
    __syncthreads();
    return nz ? 0 : 1;
}

// ---------------------------------------------------------------------------
// hist + rank: the ONLY atomic pass. rank = old degree count.
// ---------------------------------------------------------------------------
__global__ void __launch_bounds__(256) hist_rank_kernel(const void* __restrict__ idx, int E) {
    int idx64 = detect_idx64((const unsigned*)idx);
    int i = blockIdx.x * blockDim.x + threadIdx.x;
    if (i >= E) return;
    int d;
    if (idx64) d = (int)((const long long*)idx)[(size_t)E + i];
    else       d = ((const int*)idx)[(size_t)E + i];
    g_rank[i] = atomicAdd(&g_deg[d], 1);
}

// ---------------------------------------------------------------------------
// Multi-block scan (coalesced): per-block exclusive into g_off, block sums
// scanned by last-arriving block into g_bsum (global-exclusive). Zeroes
// g_deg inline and resets g_done — no scan3 pass needed.
// ---------------------------------------------------------------------------
__global__ void scan1_kernel(int nblocks, int n) {
    __shared__ int sh[256];
    int tid = threadIdx.x;
    int i = blockIdx.x * 256 + tid;
    int v = 0;
    if (i < n) {
        v = g_deg[i];
        g_deg[i] = 0;            // restore invariant for next call
    }
    sh[tid] = v;
    __syncthreads();
#pragma unroll
    for (int off = 1; off < 256; off <<= 1) {
        int x = (tid >= off) ? sh[tid - off] : 0;
        __syncthreads();
        sh[tid] += x;
        __syncthreads();
    }
    if (i < n) g_off[i] = sh[tid] - v;           // exclusive within block
    if (tid == 255) g_bsum[blockIdx.x] = sh[255];

    __shared__ int is_last;
    __threadfence();
    if (tid == 0) is_last = (atomicAdd(&g_done, 1) == nblocks - 1) ? 1 : 0;
    __syncthreads();
    if (is_last) {
        int bv = (tid < nblocks) ? g_bsum[tid] : 0;
        sh[tid] = bv;
        __syncthreads();
#pragma unroll
        for (int off = 1; off < 256; off <<= 1) {
            int x = (tid >= off) ? sh[tid - off] : 0;
            __syncthreads();
            sh[tid] += x;
            __syncthreads();
        }
        if (tid < nblocks) g_bsum[tid] = sh[tid] - bv;   // global-exclusive
        if (tid == 0) g_done = 0;                        // restore invariant
    }
}

// ---------------------------------------------------------------------------
// place: no atomics. pos = off_local[dst] + bsum[dst>>8] + rank.
// ---------------------------------------------------------------------------
__global__ void __launch_bounds__(256) place_kernel(const void* __restrict__ idx, int E) {
    int idx64 = detect_idx64((const unsigned*)idx);
    int e = blockIdx.x * blockDim.x + threadIdx.x;
    if (e >= E) return;
    int s, d;
    if (idx64) {
        const long long* p = (const long long*)idx;
        s = (int)p[e];
        d = (int)p[(size_t)E + e];
    } else {
        const int* p = (const int*)idx;
        s = p[e];
        d = p[(size_t)E + e];
    }
    int pos = __ldg(&g_off[d]) + __ldg(&g_bsum[d >> 8]) + g_rank[e];
    g_csrc[pos] = s;
}

// ---------------------------------------------------------------------------
// Dual GEMM via mma.sync.m16n8k16 (fp16 in, fp32 acc).
// Block: 128 M-rows, 256 threads (8 warps = 4m x 2n; warp tile 32x64).
// B = [Wroot | Wnbr] staged as 64x128 fp16. warp_n==0 -> Omain (fp32 + bias),
// warp_n==1 -> Ot (fp16). SMEM XOR-swizzled for conflict-free ldmatrix.
// ---------------------------------------------------------------------------
__device__ __forceinline__ uint32_t smem_u32(const void* p) {
    return (uint32_t)__cvta_generic_to_shared(p);
}

__device__ __forceinline__ void ldm_x4(uint32_t* r, uint32_t addr) {
    asm volatile("ldmatrix.sync.aligned.m8n8.x4.shared.b16 {%0,%1,%2,%3}, [%4];"
                 : "=r"(r[0]), "=r"(r[1]), "=r"(r[2]), "=r"(r[3]) : "r"(addr));
}
__device__ __forceinline__ void ldm_x4_t(uint32_t* r, uint32_t addr) {
    asm volatile("ldmatrix.sync.aligned.m8n8.x4.trans.shared.b16 {%0,%1,%2,%3}, [%4];"
                 : "=r"(r[0]), "=r"(r[1]), "=r"(r[2]), "=r"(r[3]) : "r"(addr));
}
__device__ __forceinline__ void mma16816(float* c, const uint32_t* a,
                                         uint32_t b0, uint32_t b1) {
    asm volatile(
        "mma.sync.aligned.m16n8k16.row.col.f32.f16.f16.f32 "
        "{%0,%1,%2,%3}, {%4,%5,%6,%7}, {%8,%9}, {%0,%1,%2,%3};"
        : "+f"(c[0]), "+f"(c[1]), "+f"(c[2]), "+f"(c[3])
        : "r"(a[0]), "r"(a[1]), "r"(a[2]), "r"(a[3]), "r"(b0), "r"(b1));
}

template <bool RELU>
__global__ void __launch_bounds__(256) gemm_dual_kernel(
    const float* __restrict__ X,
    const float* __restrict__ Wroot,
    const float* __restrict__ Wnbr,
    const float* __restrict__ bias,
    float* __restrict__ Omain,
    __half* __restrict__ Ot,
    int n)
{
    __shared__ __align__(16) __half sX[128 * 64];    // row stride 64h = 8 chunks
    __shared__ __align__(16) __half sW[64 * 128];    // row stride 128h = 16 chunks
    __shared__ float sBias[64];

    const int tid = threadIdx.x;
    const int row0 = blockIdx.x * 128;

    // ---- stage X (fp32 -> fp16, optional relu, swizzled): 1024 chunks ----
#pragma unroll
    for (int i = 0; i < 4; i++) {
        int idx = tid + 256 * i;          // 0..1023
        int r = idx >> 3;                 // local row 0..127
        int c8 = idx & 7;                 // 16B chunk 0..7
        int grow = row0 + r;
        float4 v0 = make_float4(0.f, 0.f, 0.f, 0.f), v1 = v0;
        if (grow < n) {
            const float4* xr = (const float4*)X + (size_t)grow * 16;
            v0 = xr[c8 * 2]; v1 = xr[c8 * 2 + 1];
        }
        if (RELU) {
            v0.x = fmaxf(v0.x, 0.f); v0.y = fmaxf(v0.y, 0.f);
            v0.z = fmaxf(v0.z, 0.f); v0.w = fmaxf(v0.w, 0.f);
            v1.x = fmaxf(v1.x, 0.f); v1.y = fmaxf(v1.y, 0.f);
            v1.z = fmaxf(v1.z, 0.f); v1.w = fmaxf(v1.w, 0.f);
        }
        __half2 hp[4];
        hp[0] = __floats2half2_rn(v0.x, v0.y);
        hp[1] = __floats2half2_rn(v0.z, v0.w);
        hp[2] = __floats2half2_rn(v1.x, v1.y);
        hp[3] = __floats2half2_rn(v1.z, v1.w);
        *(uint4*)&sX[r * 64 + ((c8 ^ (r & 7)) << 3)] = *(uint4*)hp;
    }

    // ---- stage W = [Wroot | Wnbr] (64 rows x 16 chunks, swizzled) ----
#pragma unroll
    for (int i = 0; i < 4; i++) {
        int idx = tid + 256 * i;          // 0..1023
        int k = idx >> 4;                 // 0..63
        int c16 = idx & 15;               // chunk 0..15
        const float* src = (c16 < 8) ? (Wroot + k * 64 + c16 * 8)
                                     : (Wnbr + k * 64 + (c16 - 8) * 8);
        float4 v0 = ((const float4*)src)[0];
        float4 v1 = ((const float4*)src)[1];
        __half2 hp[4];
        hp[0] = __floats2half2_rn(v0.x, v0.y);
        hp[1] = __floats2half2_rn(v0.z, v0.w);
        hp[2] = __floats2half2_rn(v1.x, v1.y);
        hp[3] = __floats2half2_rn(v1.z, v1.w);
        *(uint4*)&sW[k * 128 + ((c16 ^ (k & 7)) << 3)] = *(uint4*)hp;
    }
    if (tid < 64) sBias[tid] = bias[tid];
    __syncthreads();

    // ---- mma phase ----
    const int lane = tid & 31;
    const int wid = tid >> 5;
    const int warp_m = wid & 3;          // 0..3 -> m 32-row slab
    const int warp_n = wid >> 2;         // 0: Omain cols 0-63, 1: Ot
    const int m_base = warp_m * 32;
    const int n_base = warp_n * 64;

    float c[2][8][4];
#pragma unroll
    for (int tm = 0; tm < 2; tm++)
#pragma unroll
        for (int nt = 0; nt < 8; nt++)
#pragma unroll
            for (int q = 0; q < 4; q++) c[tm][nt][q] = 0.f;

    const uint32_t sX_base = smem_u32(sX);
    const uint32_t sW_base = smem_u32(sW);

#pragma unroll
    for (int ks = 0; ks < 4; ks++) {
        uint32_t a[2][4];
#pragma unroll
        for (int tm = 0; tm < 2; tm++) {
            int rl = m_base + tm * 16 + (lane & 15);
            int kchunk = ks * 2 + (lane >> 4);
            uint32_t off = rl * 64 + ((kchunk ^ (rl & 7)) << 3);
            ldm_x4(a[tm], sX_base + off * 2);
        }
        uint32_t b[4][4];
#pragma unroll
        for (int np = 0; np < 4; np++) {
            int rk = ks * 16 + (lane & 15);
            int nchunk = (n_base >> 3) + np * 2 + (lane >> 4);
            uint32_t off = rk * 128 + ((nchunk ^ (rk & 7)) << 3);
            ldm_x4_t(b[np], sW_base + off * 2);
        }
#pragma unroll
        for (int tm = 0; tm < 2; tm++)
#pragma unroll
            for (int np = 0; np < 4; np++) {
                mma16816(c[tm][2 * np],     a[tm], b[np][0], b[np][1]);
                mma16816(c[tm][2 * np + 1], a[tm], b[np][2], b[np][3]);
            }
    }

    // ---- epilogue ----
    const int groupID = lane >> 2;
    const int tq = lane & 3;
#pragma unroll
    for (int tm = 0; tm < 2; tm++) {
#pragma unroll
        for (int nt = 0; nt < 8; nt++) {
            int col = nt * 8 + tq * 2;               // within this warp's 64 cols
            int r0g = row0 + m_base + tm * 16 + groupID;
            int r1g = r0g + 8;
            if (warp_n == 0) {
                float2 bv = *(float2*)&sBias[col];
                if (r0g < n) {
                    float2 o = make_float2(c[tm][nt][0] + bv.x, c[tm][nt][1] + bv.y);
                    *(float2*)(Omain + (size_t)r0g * 64 + col) = o;
                }
                if (r1g < n) {
                    float2 o = make_float2(c[tm][nt][2] + bv.x, c[tm][nt][3] + bv.y);
                    *(float2*)(Omain + (size_t)r1g * 64 + col) = o;
                }
            } else {
                if (r0g < n)
                    *(__half2*)(Ot + (size_t)r0g * 64 + col) =
                        __floats2half2_rn(c[tm][nt][0], c[tm][nt][1]);
                if (r1g < n)
                    *(__half2*)(Ot + (size_t)r1g * 64 + col) =
                        __floats2half2_rn(c[tm][nt][2], c[tm][nt][3]);
            }
        }
    }
}

// ---------------------------------------------------------------------------
// CSR gather-aggregate (fp16 t): 8 lanes per node, 16B (8 halves) per lane.
// out[i] += sum t[csrc[...]]  — fp32 accumulate. Offsets reconstructed as
// off_local + bsum (scan3 was folded away).
// ---------------------------------------------------------------------------
__global__ void __launch_bounds__(256) agg_kernel(
    const __half* __restrict__ t, float* __restrict__ out, int n, int E)
{
    int gid = blockIdx.x * blockDim.x + threadIdx.x;
    int node = gid >> 3;
    if (node >= n) return;
    int part = threadIdx.x & 7;

    int start = __ldg(&g_off[node]) + __ldg(&g_bsum[node >> 8]);
    int end = (node == n - 1)
                ? E
                : __ldg(&g_off[node + 1]) + __ldg(&g_bsum[(node + 1) >> 8]);

    const uint4* tH = (const uint4*)t;
    float acc[8] = {0.f, 0.f, 0.f, 0.f, 0.f, 0.f, 0.f, 0.f};

    int j = start;
    for (; j + 4 <= end; j += 4) {
        int s0 = __ldg(&g_csrc[j]);
        int s1 = __ldg(&g_csrc[j + 1]);
        int s2 = __ldg(&g_csrc[j + 2]);
        int s3 = __ldg(&g_csrc[j + 3]);
        uint4 r0 = tH[(size_t)s0 * 8 + part];
        uint4 r1 = tH[(size_t)s1 * 8 + part];
        uint4 r2 = tH[(size_t)s2 * 8 + part];
        uint4 r3 = tH[(size_t)s3 * 8 + part];
        const uint4 rr[4] = {r0, r1, r2, r3};
#pragma unroll
        for (int q = 0; q < 4; q++) {
            const __half2* hp = (const __half2*)&rr[q];
#pragma unroll
            for (int cidx = 0; cidx < 4; cidx++) {
                float2 f = __half22float2(hp[cidx]);
                acc[2 * cidx]     += f.x;
                acc[2 * cidx + 1] += f.y;
            }
        }
    }
    for (; j < end; j++) {
        int s = __ldg(&g_csrc[j]);
        uint4 r = tH[(size_t)s * 8 + part];
        const __half2* hp = (const __half2*)&r;
#pragma unroll
        for (int cidx = 0; cidx < 4; cidx++) {
            float2 f = __half22float2(hp[cidx]);
            acc[2 * cidx]     += f.x;
            acc[2 * cidx + 1] += f.y;
        }
    }

    float4* o4 = (float4*)(out + (size_t)node * 64 + part * 8);
    float4 c0 = o4[0], c1 = o4[1];
    c0.x += acc[0]; c0.y += acc[1]; c0.z += acc[2]; c0.w += acc[3];
    c1.x += acc[4]; c1.y += acc[5]; c1.z += acc[6]; c1.w += acc[7];
    o4[0] = c0; o4[1] = c1;
}

// ---------------------------------------------------------------------------
extern "C" void kernel_launch(void* const* d_in, const int* in_sizes, int n_in,
                              void* d_out, int out_size)
{
    const float* x      = (const float*)d_in[0];
    const void*  eidx   = d_in[1];
    const float* W1root = (const float*)d_in[2];
    const float* W1nbr  = (const float*)d_in[3];
    const float* b1     = (const float*)d_in[4];
    const float* W2root = (const float*)d_in[5];
    const float* W2nbr  = (const float*)d_in[6];
    const float* b2     = (const float*)d_in[7];
    float* out = (float*)d_out;

    const int n = in_sizes[0] / DD;     // 50000
    const int E = in_sizes[1] / 2;      // 800000

    float* hptr;
    __half* tptr;
    cudaGetSymbolAddress((void**)&hptr, g_h);
    cudaGetSymbolAddress((void**)&tptr, g_t);

    const int edge_blocks = (E + 255) / 256;
    const int scan_blocks = (n + 255) / 256;          // 196
    const int gemm_blocks = (n + 127) / 128;
    const int agg_blocks  = (n * 8 + 255) / 256;

    static cudaStream_t s_side = nullptr;
    static cudaEvent_t  ev_fork = nullptr, ev_join = nullptr;
    if (s_side == nullptr) {
        cudaStreamCreateWithFlags(&s_side, cudaStreamNonBlocking);
        cudaEventCreateWithFlags(&ev_fork, cudaEventDisableTiming);
        cudaEventCreateWithFlags(&ev_join, cudaEventDisableTiming);
    }

    // ---- fork: CSR build on side stream, concurrent with gemm1 ----
    cudaEventRecord(ev_fork, cudaStreamPerThread);
    cudaStreamWaitEvent(s_side, ev_fork, 0);

    hist_rank_kernel<<<edge_blocks, 256, 0, s_side>>>(eidx, E);
    scan1_kernel    <<<scan_blocks, 256, 0, s_side>>>(scan_blocks, n);
    place_kernel    <<<edge_blocks, 256, 0, s_side>>>(eidx, E);
    cudaEventRecord(ev_join, s_side);

    // ---- main stream: layer-1 GEMM in parallel with CSR build ----
    gemm_dual_kernel<false><<<gemm_blocks, 256>>>(x, W1root, W1nbr, b1, hptr, tptr, n);

    // join: agg1 needs both CSR and t1
    cudaStreamWaitEvent(cudaStreamPerThread, ev_join, 0);
    agg_kernel<<<agg_blocks, 256>>>(tptr, hptr, n, E);

    // ---- Layer 2 ----
    gemm_dual_kernel<true><<<gemm_blocks, 256>>>(hptr, W2root, W2nbr, b2, out, tptr, n);
    agg_kernel<<<agg_blocks, 256>>>(tptr, out, n, E);
}